// round 10
// baseline (speedup 1.0000x reference)
#include <cuda_runtime.h>
#include <math.h>

// Shapes (fixed by the problem)
#define BB  2
#define NN  512
#define HID 128
#define DD  32    // Chebyshev orders; measured: truncation below fp32 noise at 32

// fused prologue tiling
#define NODES 4                    // Chebyshev nodes per block
#define KSPL  4                    // k-dimension split
#define NE_BLOCKS (DD / NODES)     // 8
#define NE_THREADS (HID * KSPL)    // 512

// Scratch (static device globals; no allocation)
__device__ float g_inv_hd;        // 2 / dmax
__device__ float g_G[DD * HID];   // network(+Wo) at Chebyshev nodes
__device__ float g_C[DD * HID];   // Chebyshev coefficients
__device__ unsigned g_arrive;     // grid barrier counter (0 at start AND end of every launch)

// ---------------------------------------------------------------------------
// Fused prologue: phase 1 = exact fp32 network at DD Chebyshev nodes (+Wo fold),
// phase 2 (after 8-block grid barrier) = DCT-II -> coefficients.
// 8 blocks x 512 threads; thread (q,c): q = k-quarter / node slot, c = column.
// Weight prefetch double-buffers the next layer's 32 LDGs under current compute.
// ---------------------------------------------------------------------------
__global__ __launch_bounds__(NE_THREADS) void prologue_kernel(
    const float* __restrict__ x,
    const float* __restrict__ W10, const float* __restrict__ b10,
    const float* __restrict__ W20, const float* __restrict__ b20,
    const float* __restrict__ W11, const float* __restrict__ b11,
    const float* __restrict__ W21, const float* __restrict__ b21,
    const float* __restrict__ W12, const float* __restrict__ b12,
    const float* __restrict__ W22, const float* __restrict__ b22,
    const float* __restrict__ Wo)
{
    __shared__ float red[NE_THREADS];
    __shared__ float buf[NODES][HID];          // current activations
    __shared__ float part[KSPL][NODES][HID];   // per-quarter partials
    __shared__ float costab[NODES][DD];        // phase 2: cos table
    __shared__ float sG[DD][HID];              // phase 2: staged G (16KB)

    const int c = threadIdx.x & (HID - 1);
    const int q = threadIdx.x >> 7;            // 0..3
    const int k0 = q * (HID / KSPL);           // 32 k's per quarter

    const float* Ws[6] = {W20, W11, W21, W12, W22, Wo};
    const float* bs[6] = {b20, b11, b21, b12, b22, (const float*)0};

    // issue layer-0 weight loads early (independent of everything below)
    float wc[HID / KSPL];
    #pragma unroll
    for (int kk = 0; kk < HID / KSPL; kk++) wc[kk] = Ws[0][(k0 + kk) * HID + c];

    // dmax = 2*max||x|| (triangle-inequality bound), deterministic per block
    float mx = 0.0f;
    for (int t = threadIdx.x; t < BB * NN; t += NE_THREADS) {
        float a = x[2 * t], b = x[2 * t + 1];
        mx = fmaxf(mx, fmaf(a, a, b * b));
    }
    red[threadIdx.x] = mx;
    __syncthreads();
    #pragma unroll
    for (int s = NE_THREADS / 2; s > 0; s >>= 1) {
        if (threadIdx.x < s) red[threadIdx.x] = fmaxf(red[threadIdx.x], red[threadIdx.x + s]);
        __syncthreads();
    }
    const float dmax = 2.0f * sqrtf(red[0]) * 1.000001f + 1e-6f;
    if (blockIdx.x == 0 && threadIdx.x == 0) g_inv_hd = 2.0f / dmax;

    // layer 0 (scalar input): thread-set q computes node q of this block
    {
        int mnode = blockIdx.x * NODES + q;
        float d = 0.5f * (cospif((mnode + 0.5f) * (1.0f / DD)) + 1.0f) * dmax;
        float a = fmaf(d, W10[c], b10[c]);
        buf[q][c] = a / (1.0f + expf(-a));
    }
    __syncthreads();

    #pragma unroll
    for (int l = 0; l < 6; l++) {
        // prefetch next layer's weights (hides LDG latency under compute+syncs)
        float wn[HID / KSPL];
        if (l < 5) {
            #pragma unroll
            for (int kk = 0; kk < HID / KSPL; kk++)
                wn[kk] = Ws[l + 1][(k0 + kk) * HID + c];
        }
        float h0 = 0.0f, h1 = 0.0f, h2 = 0.0f, h3 = 0.0f;
        #pragma unroll
        for (int kk = 0; kk < HID / KSPL; kk++) {
            const int k = k0 + kk;
            const float w = wc[kk];
            h0 = fmaf(buf[0][k], w, h0);
            h1 = fmaf(buf[1][k], w, h1);
            h2 = fmaf(buf[2][k], w, h2);
            h3 = fmaf(buf[3][k], w, h3);
        }
        part[q][0][c] = h0;
        part[q][1][c] = h1;
        part[q][2][c] = h2;
        part[q][3][c] = h3;
        __syncthreads();
        float v = (bs[l] ? bs[l][c] : 0.0f) +
                  ((part[0][q][c] + part[1][q][c]) + (part[2][q][c] + part[3][q][c]));
        if (l == 1 || l == 3) v = v / (1.0f + expf(-v));   // silu after W1_1, W1_2
        if (l < 5) buf[q][c] = v;                          // reads of buf done pre-sync
        else g_G[(blockIdx.x * NODES + q) * HID + c] = v;
        __syncthreads();
        #pragma unroll
        for (int kk = 0; kk < HID / KSPL; kk++) wc[kk] = wn[kk];
    }

    // ---- grid barrier across the 8 co-resident blocks (replay-safe) ----
    __threadfence();
    if (threadIdx.x == 0) {
        atomicAdd(&g_arrive, 1u);
        while (*(volatile unsigned*)&g_arrive < (unsigned)NE_BLOCKS) __nanosleep(32);
    }
    __syncthreads();
    __threadfence();

    // ---- phase 2: DCT-II. Block handles k = blockIdx*4 + q. ----
    for (int t = threadIdx.x; t < NODES * DD; t += NE_THREADS) {
        int qq = t / DD, m = t - qq * DD;
        int k = blockIdx.x * NODES + qq;
        int num = (k * (2 * m + 1)) & (4 * DD - 1);   // cospi period 2 -> mod 128
        costab[qq][m] = cospif((float)num * (1.0f / (2.0f * DD)));
    }
    for (int t = threadIdx.x; t < DD * HID / 4; t += NE_THREADS)
        reinterpret_cast<float4*>(sG)[t] =
            __ldcg(reinterpret_cast<const float4*>(g_G) + t);
    __syncthreads();

    {
        int k = blockIdx.x * NODES + q;
        float acc = 0.0f;
        #pragma unroll
        for (int m = 0; m < DD; m++) acc = fmaf(costab[q][m], sG[m][c], acc);
        float wgt = (k == 0) ? (1.0f / DD) : (2.0f / DD);
        g_C[k * HID + c] = acc * wgt;
    }

    // exit: restore barrier counter to 0 for the next graph replay
    __syncthreads();
    if (threadIdx.x == 0) atomicSub(&g_arrive, 1u);
}

// ---------------------------------------------------------------------------
// Hot kernel: per (b,i), s[k] = sum_j T_k(z_ij); out = (1/N) s@C + bo.
// 512 blocks x 128 thr: block = 2 rows x 2 warps/row (j-split 256 each).
// Parity-split recurrences (T_{k+2} = y T_k - T_{k-2}, y = 4z^2-2): 8
// independent lat-4 FMA chains per lane -> latency fully hidden at low occ.
// Coefficients prefetched to smem via cp.async at block start (tail removed).
// ---------------------------------------------------------------------------
__global__ __launch_bounds__(128, 8) void cheb_main_kernel(
    const float* __restrict__ x, const float* __restrict__ bo,
    float* __restrict__ out)
{
    __shared__ float sx[NN * 2];
    __shared__ float sred[4][DD];          // per-warp reduced s
    __shared__ float sC[DD * HID];         // prefetched coefficients (16KB)

    const float inv_hd = g_inv_hd;         // published by prologue

    // prefetch C into smem (cp.async: no register cost, overlaps main loop)
    {
        unsigned sa = (unsigned)__cvta_generic_to_shared(sC) + threadIdx.x * 16u;
        const float4* gp = reinterpret_cast<const float4*>(g_C) + threadIdx.x;
        #pragma unroll
        for (int it = 0; it < DD * HID / 4 / 128; it++) {
            asm volatile("cp.async.cg.shared.global [%0], [%1], 16;\n"
                         :: "r"(sa + it * 128u * 16u), "l"(gp + it * 128) : "memory");
        }
        asm volatile("cp.async.commit_group;\n" ::: "memory");
    }

    const int b = blockIdx.x >> 8;         // 256 blocks per batch
    for (int t = threadIdx.x; t < NN * 2; t += 128) sx[t] = x[b * NN * 2 + t];
    __syncthreads();

    const int w    = threadIdx.x >> 5;     // warp 0..3
    const int lane = threadIdx.x & 31;
    const int r    = w >> 1;               // row-in-block 0..1
    const int h    = w & 1;                // j-half 0..1
    const int i    = ((blockIdx.x & 255) << 1) + r;   // row within batch
    const float xi0 = sx[2 * i], xi1 = sx[2 * i + 1];

    float s[DD];
    #pragma unroll
    for (int k = 0; k < DD; k++) s[k] = 0.0f;

    #pragma unroll 1
    for (int jj = 0; jj < 2; jj++) {
        const int j0 = h * 256 + jj * 128;
        const int ja = j0 + lane, jb = ja + 32, jc = ja + 64, jd = ja + 96;
        float dxa = xi0 - sx[2 * ja], dya = xi1 - sx[2 * ja + 1];
        float dxb = xi0 - sx[2 * jb], dyb = xi1 - sx[2 * jb + 1];
        float dxc = xi0 - sx[2 * jc], dyc = xi1 - sx[2 * jc + 1];
        float dxd = xi0 - sx[2 * jd], dyd = xi1 - sx[2 * jd + 1];
        float za = fmaf(sqrtf(fmaf(dxa, dxa, dya * dya)), inv_hd, -1.0f);
        float zb = fmaf(sqrtf(fmaf(dxb, dxb, dyb * dyb)), inv_hd, -1.0f);
        float zc = fmaf(sqrtf(fmaf(dxc, dxc, dyc * dyc)), inv_hd, -1.0f);
        float zd = fmaf(sqrtf(fmaf(dxd, dxd, dyd * dyd)), inv_hd, -1.0f);
        za = fminf(fmaxf(za, -1.0f), 1.0f);
        zb = fminf(fmaxf(zb, -1.0f), 1.0f);
        zc = fminf(fmaxf(zc, -1.0f), 1.0f);
        zd = fminf(fmaxf(zd, -1.0f), 1.0f);

        // seeds: T1 = z, T2 = 2z^2-1, T3 = y*z - z, y = 2*T2
        float e1a = fmaf(za + za, za, -1.0f), ya = e1a + e1a;
        float e1b = fmaf(zb + zb, zb, -1.0f), yb = e1b + e1b;
        float e1c = fmaf(zc + zc, zc, -1.0f), yc = e1c + e1c;
        float e1d = fmaf(zd + zd, zd, -1.0f), yd = e1d + e1d;
        float o1a = fmaf(ya, za, -za);
        float o1b = fmaf(yb, zb, -zb);
        float o1c = fmaf(yc, zc, -zc);
        float o1d = fmaf(yd, zd, -zd);
        s[1] += (za + zb) + (zc + zd);
        s[2] += (e1a + e1b) + (e1c + e1d);
        s[3] += (o1a + o1b) + (o1c + o1d);

        float e0a = 1.0f, e0b = 1.0f, e0c = 1.0f, e0d = 1.0f;
        float o0a = za,   o0b = zb,   o0c = zc,   o0d = zd;
        #pragma unroll
        for (int j = 2; j < DD / 2; j++) {
            float ea = fmaf(ya, e1a, -e0a); e0a = e1a; e1a = ea;
            float eb = fmaf(yb, e1b, -e0b); e0b = e1b; e1b = eb;
            float ec = fmaf(yc, e1c, -e0c); e0c = e1c; e1c = ec;
            float ed = fmaf(yd, e1d, -e0d); e0d = e1d; e1d = ed;
            float oa = fmaf(ya, o1a, -o0a); o0a = o1a; o1a = oa;
            float ob = fmaf(yb, o1b, -o0b); o0b = o1b; o1b = ob;
            float oc = fmaf(yc, o1c, -o0c); o0c = o1c; o1c = oc;
            float od = fmaf(yd, o1d, -o0d); o0d = o1d; o1d = od;
            s[2 * j]     += (ea + eb) + (ec + ed);
            s[2 * j + 1] += (oa + ob) + (oc + od);
        }
    }
    // T_0 == 1: each lane processed 256/32 = 8 source nodes
    s[0] = 8.0f;

    // reduce-scatter butterfly over 32 elements: lane ends holding k = lane
    int len = DD / 2;
    #pragma unroll
    for (int off = 16; off > 0; off >>= 1) {
        const bool hi = (lane & off) != 0;
        #pragma unroll
        for (int k = 0; k < 16; k++) {
            if (k >= len) break;
            float send = hi ? s[k] : s[k + len];
            float recv = __shfl_xor_sync(0xffffffffu, send, off);
            s[k] = (hi ? s[k + len] : s[k]) + recv;
        }
        len >>= 1;
    }
    sred[w][lane] = s[0];

    // C prefetch must have landed; also orders sred stores
    asm volatile("cp.async.wait_group 0;\n" ::: "memory");
    __syncthreads();

    // combine the row's two j-halves and contract with C.
    // Each warp handles 64 of the row's 128 output columns (float2 per lane).
    const float sc = 1.0f / (float)NN;
    const int c0 = h * 64 + lane * 2;
    float accx = bo[c0], accy = bo[c0 + 1];
    #pragma unroll
    for (int k = 0; k < DD; k++) {
        float sk = (sred[2 * r][k] + sred[2 * r + 1][k]) * sc;
        float2 wv = *reinterpret_cast<const float2*>(&sC[k * HID + c0]);
        accx = fmaf(sk, wv.x, accx);
        accy = fmaf(sk, wv.y, accy);
    }
    const int gi = b * NN + i;
    *reinterpret_cast<float2*>(&out[gi * HID + c0]) = make_float2(accx, accy);
}

// ---------------------------------------------------------------------------
// Launch: 2 graph-capturable kernels.
// Input order: x, W1_0,b1_0,W2_0,b2_0, W1_1,b1_1,W2_1,b2_1, W1_2,b1_2,W2_2,b2_2, Wo,bo
// ---------------------------------------------------------------------------
extern "C" void kernel_launch(void* const* d_in, const int* in_sizes, int n_in,
                              void* d_out, int out_size)
{
    const float* x   = (const float*)d_in[0];
    const float* W10 = (const float*)d_in[1];
    const float* b10 = (const float*)d_in[2];
    const float* W20 = (const float*)d_in[3];
    const float* b20 = (const float*)d_in[4];
    const float* W11 = (const float*)d_in[5];
    const float* b11 = (const float*)d_in[6];
    const float* W21 = (const float*)d_in[7];
    const float* b21 = (const float*)d_in[8];
    const float* W12 = (const float*)d_in[9];
    const float* b12 = (const float*)d_in[10];
    const float* W22 = (const float*)d_in[11];
    const float* b22 = (const float*)d_in[12];
    const float* Wo  = (const float*)d_in[13];
    const float* bo  = (const float*)d_in[14];
    float* out = (float*)d_out;

    prologue_kernel<<<NE_BLOCKS, NE_THREADS>>>(x, W10, b10, W20, b20, W11, b11,
                                               W21, b21, W12, b12, W22, b22, Wo);
    cheb_main_kernel<<<(BB * NN) / 2, 128>>>(x, bo, out);
}

// round 11
// speedup vs baseline: 1.0482x; 1.0482x over previous
#include <cuda_runtime.h>
#include <math.h>

// Shapes (fixed by the problem)
#define BB  2
#define NN  512
#define HID 128
#define DD  32    // Chebyshev orders; measured: truncation below fp32 noise at 32

// fused prologue tiling
#define NODES 4                    // Chebyshev nodes per block
#define KSPL  4                    // k-dimension split
#define NE_BLOCKS (DD / NODES)     // 8
#define NE_THREADS (HID * KSPL)    // 512

// Scratch (static device globals; no allocation)
__device__ float g_inv_hd;        // 2 / dmax
__device__ float g_G[DD * HID];   // network(+Wo) at Chebyshev nodes
__device__ float g_C[DD * HID];   // Chebyshev coefficients
__device__ unsigned g_arrive;     // grid barrier counter (0 at start AND end of every launch)

// ---------------------------------------------------------------------------
// Fused prologue: phase 1 = exact fp32 network at DD Chebyshev nodes (+Wo fold),
// phase 2 (after 8-block grid barrier) = DCT-II -> coefficients.
// 8 blocks x 512 threads; thread (q,c): q = k-quarter / node slot, c = column.
// Weight prefetch double-buffers the next layer's 32 LDGs under current compute.
// ---------------------------------------------------------------------------
__global__ __launch_bounds__(NE_THREADS) void prologue_kernel(
    const float* __restrict__ x,
    const float* __restrict__ W10, const float* __restrict__ b10,
    const float* __restrict__ W20, const float* __restrict__ b20,
    const float* __restrict__ W11, const float* __restrict__ b11,
    const float* __restrict__ W21, const float* __restrict__ b21,
    const float* __restrict__ W12, const float* __restrict__ b12,
    const float* __restrict__ W22, const float* __restrict__ b22,
    const float* __restrict__ Wo)
{
    __shared__ float red[NE_THREADS];
    __shared__ float buf[NODES][HID];          // current activations
    __shared__ float part[KSPL][NODES][HID];   // per-quarter partials
    __shared__ float costab[NODES][DD];        // phase 2: cos table
    __shared__ float sG[DD][HID];              // phase 2: staged G (16KB)

    const int c = threadIdx.x & (HID - 1);
    const int q = threadIdx.x >> 7;            // 0..3
    const int k0 = q * (HID / KSPL);           // 32 k's per quarter

    const float* Ws[6] = {W20, W11, W21, W12, W22, Wo};
    const float* bs[6] = {b20, b11, b21, b12, b22, (const float*)0};

    // issue layer-0 weight loads early (independent of everything below)
    float wc[HID / KSPL];
    #pragma unroll
    for (int kk = 0; kk < HID / KSPL; kk++) wc[kk] = Ws[0][(k0 + kk) * HID + c];

    // dmax = 2*max||x|| (triangle-inequality bound), deterministic per block
    float mx = 0.0f;
    for (int t = threadIdx.x; t < BB * NN; t += NE_THREADS) {
        float a = x[2 * t], b = x[2 * t + 1];
        mx = fmaxf(mx, fmaf(a, a, b * b));
    }
    red[threadIdx.x] = mx;
    __syncthreads();
    #pragma unroll
    for (int s = NE_THREADS / 2; s > 0; s >>= 1) {
        if (threadIdx.x < s) red[threadIdx.x] = fmaxf(red[threadIdx.x], red[threadIdx.x + s]);
        __syncthreads();
    }
    const float dmax = 2.0f * sqrtf(red[0]) * 1.000001f + 1e-6f;
    if (blockIdx.x == 0 && threadIdx.x == 0) g_inv_hd = 2.0f / dmax;

    // layer 0 (scalar input): thread-set q computes node q of this block
    {
        int mnode = blockIdx.x * NODES + q;
        float d = 0.5f * (cospif((mnode + 0.5f) * (1.0f / DD)) + 1.0f) * dmax;
        float a = fmaf(d, W10[c], b10[c]);
        buf[q][c] = a / (1.0f + expf(-a));
    }
    __syncthreads();

    #pragma unroll
    for (int l = 0; l < 6; l++) {
        // prefetch next layer's weights (hides LDG latency under compute+syncs)
        float wn[HID / KSPL];
        if (l < 5) {
            #pragma unroll
            for (int kk = 0; kk < HID / KSPL; kk++)
                wn[kk] = Ws[l + 1][(k0 + kk) * HID + c];
        }
        float h0 = 0.0f, h1 = 0.0f, h2 = 0.0f, h3 = 0.0f;
        #pragma unroll
        for (int kk = 0; kk < HID / KSPL; kk++) {
            const int k = k0 + kk;
            const float w = wc[kk];
            h0 = fmaf(buf[0][k], w, h0);
            h1 = fmaf(buf[1][k], w, h1);
            h2 = fmaf(buf[2][k], w, h2);
            h3 = fmaf(buf[3][k], w, h3);
        }
        part[q][0][c] = h0;
        part[q][1][c] = h1;
        part[q][2][c] = h2;
        part[q][3][c] = h3;
        __syncthreads();
        float v = (bs[l] ? bs[l][c] : 0.0f) +
                  ((part[0][q][c] + part[1][q][c]) + (part[2][q][c] + part[3][q][c]));
        if (l == 1 || l == 3) v = v / (1.0f + expf(-v));   // silu after W1_1, W1_2
        if (l < 5) buf[q][c] = v;                          // reads of buf done pre-sync
        else g_G[(blockIdx.x * NODES + q) * HID + c] = v;
        __syncthreads();
        #pragma unroll
        for (int kk = 0; kk < HID / KSPL; kk++) wc[kk] = wn[kk];
    }

    // ---- grid barrier across the 8 co-resident blocks (replay-safe) ----
    __threadfence();
    if (threadIdx.x == 0) {
        atomicAdd(&g_arrive, 1u);
        while (*(volatile unsigned*)&g_arrive < (unsigned)NE_BLOCKS) __nanosleep(32);
    }
    __syncthreads();
    __threadfence();

    // ---- phase 2: DCT-II. Block handles k = blockIdx*4 + q. ----
    for (int t = threadIdx.x; t < NODES * DD; t += NE_THREADS) {
        int qq = t / DD, m = t - qq * DD;
        int k = blockIdx.x * NODES + qq;
        int num = (k * (2 * m + 1)) & (4 * DD - 1);   // cospi period 2 -> mod 128
        costab[qq][m] = cospif((float)num * (1.0f / (2.0f * DD)));
    }
    for (int t = threadIdx.x; t < DD * HID / 4; t += NE_THREADS)
        reinterpret_cast<float4*>(sG)[t] =
            __ldcg(reinterpret_cast<const float4*>(g_G) + t);
    __syncthreads();

    {
        int k = blockIdx.x * NODES + q;
        float acc = 0.0f;
        #pragma unroll
        for (int m = 0; m < DD; m++) acc = fmaf(costab[q][m], sG[m][c], acc);
        float wgt = (k == 0) ? (1.0f / DD) : (2.0f / DD);
        g_C[k * HID + c] = acc * wgt;
    }

    // exit: restore barrier counter to 0 for the next graph replay
    __syncthreads();
    if (threadIdx.x == 0) atomicSub(&g_arrive, 1u);
}

// ---------------------------------------------------------------------------
// Hot kernel: per (b,i), s[k] = sum_j T_k(z_ij); out = (1/N) s@C + bo.
// 512 blocks x 256 thr: block = 2 rows x 4 warps/row (j-split 128 each).
// 4 independent lat-4 recurrence chains per lane; single inner pass.
// 4096 warps chip-wide (~7/SMSP) -> issue slots actually fillable.
// ---------------------------------------------------------------------------
__global__ __launch_bounds__(256, 4) void cheb_main_kernel(
    const float* __restrict__ x, const float* __restrict__ bo,
    float* __restrict__ out)
{
    __shared__ float sx[NN * 2];
    __shared__ float sred[8][DD];          // per-warp reduced s
    __shared__ float sredc[2][DD];         // per-row combined s

    const float inv_hd = g_inv_hd;         // published by prologue

    const int b = blockIdx.x >> 8;         // 256 blocks per batch
    for (int t = threadIdx.x; t < NN * 2; t += 256) sx[t] = x[b * NN * 2 + t];
    __syncthreads();

    const int w    = threadIdx.x >> 5;     // warp 0..7
    const int lane = threadIdx.x & 31;
    const int r    = w >> 2;               // row-in-block 0..1
    const int h    = w & 3;                // j-quarter 0..3
    const int i    = ((blockIdx.x & 255) << 1) + r;   // row within batch
    const float xi0 = sx[2 * i], xi1 = sx[2 * i + 1];

    float s[DD];
    #pragma unroll
    for (int k = 2; k < DD; k++) s[k] = 0.0f;

    {
        const int j0 = h * 128;
        const int ja = j0 + lane, jb = ja + 32, jc = ja + 64, jd = ja + 96;
        float dxa = xi0 - sx[2 * ja], dya = xi1 - sx[2 * ja + 1];
        float dxb = xi0 - sx[2 * jb], dyb = xi1 - sx[2 * jb + 1];
        float dxc = xi0 - sx[2 * jc], dyc = xi1 - sx[2 * jc + 1];
        float dxd = xi0 - sx[2 * jd], dyd = xi1 - sx[2 * jd + 1];
        float za = fmaf(sqrtf(fmaf(dxa, dxa, dya * dya)), inv_hd, -1.0f);
        float zb = fmaf(sqrtf(fmaf(dxb, dxb, dyb * dyb)), inv_hd, -1.0f);
        float zc = fmaf(sqrtf(fmaf(dxc, dxc, dyc * dyc)), inv_hd, -1.0f);
        float zd = fmaf(sqrtf(fmaf(dxd, dxd, dyd * dyd)), inv_hd, -1.0f);
        za = fminf(fmaxf(za, -1.0f), 1.0f);
        zb = fminf(fmaxf(zb, -1.0f), 1.0f);
        zc = fminf(fmaxf(zc, -1.0f), 1.0f);
        zd = fminf(fmaxf(zd, -1.0f), 1.0f);

        s[1] = (za + zb) + (zc + zd);
        float t0a = 1.0f, t1a = za, z2a = za + za;
        float t0b = 1.0f, t1b = zb, z2b = zb + zb;
        float t0c = 1.0f, t1c = zc, z2c = zc + zc;
        float t0d = 1.0f, t1d = zd, z2d = zd + zd;
        #pragma unroll
        for (int k = 2; k < DD; k++) {
            float ta = fmaf(z2a, t1a, -t0a); t0a = t1a; t1a = ta;
            float tb = fmaf(z2b, t1b, -t0b); t0b = t1b; t1b = tb;
            float tc = fmaf(z2c, t1c, -t0c); t0c = t1c; t1c = tc;
            float td = fmaf(z2d, t1d, -t0d); t0d = t1d; t1d = td;
            s[k] += (ta + tb) + (tc + td);
        }
    }
    // T_0 == 1: each lane processed 128/32 = 4 source nodes
    s[0] = 4.0f;

    // reduce-scatter butterfly over 32 elements: lane ends holding k = lane
    int len = DD / 2;
    #pragma unroll
    for (int off = 16; off > 0; off >>= 1) {
        const bool hi = (lane & off) != 0;
        #pragma unroll
        for (int k = 0; k < 16; k++) {
            if (k >= len) break;
            float send = hi ? s[k] : s[k + len];
            float recv = __shfl_xor_sync(0xffffffffu, send, off);
            s[k] = (hi ? s[k + len] : s[k]) + recv;
        }
        len >>= 1;
    }
    sred[w][lane] = s[0];
    __syncthreads();

    // combine the 4 j-quarters per row (deterministic sequential order)
    if (threadIdx.x < 2 * DD) {
        const int rr = threadIdx.x >> 5, kk = threadIdx.x & 31;
        sredc[rr][kk] = ((sred[4 * rr][kk]     + sred[4 * rr + 1][kk])
                       + (sred[4 * rr + 2][kk] + sred[4 * rr + 3][kk]))
                        * (1.0f / (float)NN);
    }
    __syncthreads();

    // contract with C: warp owns 32 columns, lane owns 1 (coalesced LDG of C)
    const int c0 = h * 32 + lane;
    float acc = bo[c0];
    #pragma unroll
    for (int k = 0; k < DD; k++)
        acc = fmaf(sredc[r][k], g_C[k * HID + c0], acc);
    const int gi = b * NN + i;
    out[gi * HID + c0] = acc;
}

// ---------------------------------------------------------------------------
// Launch: 2 graph-capturable kernels.
// Input order: x, W1_0,b1_0,W2_0,b2_0, W1_1,b1_1,W2_1,b2_1, W1_2,b1_2,W2_2,b2_2, Wo,bo
// ---------------------------------------------------------------------------
extern "C" void kernel_launch(void* const* d_in, const int* in_sizes, int n_in,
                              void* d_out, int out_size)
{
    const float* x   = (const float*)d_in[0];
    const float* W10 = (const float*)d_in[1];
    const float* b10 = (const float*)d_in[2];
    const float* W20 = (const float*)d_in[3];
    const float* b20 = (const float*)d_in[4];
    const float* W11 = (const float*)d_in[5];
    const float* b11 = (const float*)d_in[6];
    const float* W21 = (const float*)d_in[7];
    const float* b21 = (const float*)d_in[8];
    const float* W12 = (const float*)d_in[9];
    const float* b12 = (const float*)d_in[10];
    const float* W22 = (const float*)d_in[11];
    const float* b22 = (const float*)d_in[12];
    const float* Wo  = (const float*)d_in[13];
    const float* bo  = (const float*)d_in[14];
    float* out = (float*)d_out;

    prologue_kernel<<<NE_BLOCKS, NE_THREADS>>>(x, W10, b10, W20, b20, W11, b11,
                                               W21, b21, W12, b12, W22, b22, Wo);
    cheb_main_kernel<<<(BB * NN) / 2, 256>>>(x, bo, out);
}

// round 12
// speedup vs baseline: 1.0498x; 1.0015x over previous
#include <cuda_runtime.h>
#include <math.h>

// Shapes (fixed by the problem)
#define BB  2
#define NN  512
#define HID 128
#define DD  32    // Chebyshev orders; measured: truncation below fp32 noise at 32

// fused prologue tiling
#define NODES 4                    // Chebyshev nodes per block
#define KSPL  4                    // k-dimension split
#define NE_BLOCKS (DD / NODES)     // 8
#define NE_THREADS (HID * KSPL)    // 512

// Scratch (static device globals; no allocation)
__device__ float g_inv_hd;        // 2 / dmax
__device__ float g_G[DD * HID];   // network(+Wo) at Chebyshev nodes
__device__ float g_C[DD * HID];   // Chebyshev coefficients
__device__ unsigned g_arrive;     // grid barrier counter (0 at start AND end of every launch)

// ---------------------------------------------------------------------------
// Fused prologue: phase 1 = exact fp32 network at DD Chebyshev nodes (+Wo fold),
// phase 2 (after 8-block grid barrier) = DCT-II -> coefficients.
// 8 blocks x 512 threads; thread (q,c): q = k-quarter / node slot, c = column.
// Weight prefetch double-buffers the next layer's 32 LDGs under current compute.
// ---------------------------------------------------------------------------
__global__ __launch_bounds__(NE_THREADS) void prologue_kernel(
    const float* __restrict__ x,
    const float* __restrict__ W10, const float* __restrict__ b10,
    const float* __restrict__ W20, const float* __restrict__ b20,
    const float* __restrict__ W11, const float* __restrict__ b11,
    const float* __restrict__ W21, const float* __restrict__ b21,
    const float* __restrict__ W12, const float* __restrict__ b12,
    const float* __restrict__ W22, const float* __restrict__ b22,
    const float* __restrict__ Wo)
{
    __shared__ float red[NE_THREADS];
    __shared__ float buf[NODES][HID];          // current activations
    __shared__ float part[KSPL][NODES][HID];   // per-quarter partials
    __shared__ float costab[NODES][DD];        // phase 2: cos table
    __shared__ float sG[DD][HID];              // phase 2: staged G (16KB)

    const int c = threadIdx.x & (HID - 1);
    const int q = threadIdx.x >> 7;            // 0..3
    const int k0 = q * (HID / KSPL);           // 32 k's per quarter

    const float* Ws[6] = {W20, W11, W21, W12, W22, Wo};
    const float* bs[6] = {b20, b11, b21, b12, b22, (const float*)0};

    // issue layer-0 weight loads early (independent of everything below)
    float wc[HID / KSPL];
    #pragma unroll
    for (int kk = 0; kk < HID / KSPL; kk++) wc[kk] = Ws[0][(k0 + kk) * HID + c];

    // dmax = 2*max||x|| (triangle-inequality bound), deterministic per block
    float mx = 0.0f;
    for (int t = threadIdx.x; t < BB * NN; t += NE_THREADS) {
        float a = x[2 * t], b = x[2 * t + 1];
        mx = fmaxf(mx, fmaf(a, a, b * b));
    }
    red[threadIdx.x] = mx;
    __syncthreads();
    #pragma unroll
    for (int s = NE_THREADS / 2; s > 0; s >>= 1) {
        if (threadIdx.x < s) red[threadIdx.x] = fmaxf(red[threadIdx.x], red[threadIdx.x + s]);
        __syncthreads();
    }
    const float dmax = 2.0f * sqrtf(red[0]) * 1.000001f + 1e-6f;
    if (blockIdx.x == 0 && threadIdx.x == 0) g_inv_hd = 2.0f / dmax;

    // layer 0 (scalar input): thread-set q computes node q of this block
    {
        int mnode = blockIdx.x * NODES + q;
        float d = 0.5f * (cospif((mnode + 0.5f) * (1.0f / DD)) + 1.0f) * dmax;
        float a = fmaf(d, W10[c], b10[c]);
        buf[q][c] = a / (1.0f + expf(-a));
    }
    __syncthreads();

    #pragma unroll
    for (int l = 0; l < 6; l++) {
        // prefetch next layer's weights (hides LDG latency under compute+syncs)
        float wn[HID / KSPL];
        if (l < 5) {
            #pragma unroll
            for (int kk = 0; kk < HID / KSPL; kk++)
                wn[kk] = Ws[l + 1][(k0 + kk) * HID + c];
        }
        float h0 = 0.0f, h1 = 0.0f, h2 = 0.0f, h3 = 0.0f;
        #pragma unroll
        for (int kk = 0; kk < HID / KSPL; kk++) {
            const int k = k0 + kk;
            const float w = wc[kk];
            h0 = fmaf(buf[0][k], w, h0);
            h1 = fmaf(buf[1][k], w, h1);
            h2 = fmaf(buf[2][k], w, h2);
            h3 = fmaf(buf[3][k], w, h3);
        }
        part[q][0][c] = h0;
        part[q][1][c] = h1;
        part[q][2][c] = h2;
        part[q][3][c] = h3;
        __syncthreads();
        float v = (bs[l] ? bs[l][c] : 0.0f) +
                  ((part[0][q][c] + part[1][q][c]) + (part[2][q][c] + part[3][q][c]));
        if (l == 1 || l == 3) v = v / (1.0f + expf(-v));   // silu after W1_1, W1_2
        if (l < 5) buf[q][c] = v;                          // reads of buf done pre-sync
        else g_G[(blockIdx.x * NODES + q) * HID + c] = v;
        __syncthreads();
        #pragma unroll
        for (int kk = 0; kk < HID / KSPL; kk++) wc[kk] = wn[kk];
    }

    // ---- grid barrier across the 8 co-resident blocks (replay-safe) ----
    __threadfence();
    if (threadIdx.x == 0) {
        atomicAdd(&g_arrive, 1u);
        while (*(volatile unsigned*)&g_arrive < (unsigned)NE_BLOCKS) __nanosleep(32);
    }
    __syncthreads();
    __threadfence();

    // ---- phase 2: DCT-II. Block handles k = blockIdx*4 + q. ----
    for (int t = threadIdx.x; t < NODES * DD; t += NE_THREADS) {
        int qq = t / DD, m = t - qq * DD;
        int k = blockIdx.x * NODES + qq;
        int num = (k * (2 * m + 1)) & (4 * DD - 1);   // cospi period 2 -> mod 128
        costab[qq][m] = cospif((float)num * (1.0f / (2.0f * DD)));
    }
    for (int t = threadIdx.x; t < DD * HID / 4; t += NE_THREADS)
        reinterpret_cast<float4*>(sG)[t] =
            __ldcg(reinterpret_cast<const float4*>(g_G) + t);
    __syncthreads();

    {
        int k = blockIdx.x * NODES + q;
        float acc = 0.0f;
        #pragma unroll
        for (int m = 0; m < DD; m++) acc = fmaf(costab[q][m], sG[m][c], acc);
        float wgt = (k == 0) ? (1.0f / DD) : (2.0f / DD);
        g_C[k * HID + c] = acc * wgt;
    }

    // exit: restore barrier counter to 0 for the next graph replay
    __syncthreads();
    if (threadIdx.x == 0) atomicSub(&g_arrive, 1u);
}

// ---------------------------------------------------------------------------
// Hot kernel: per (b,i), s[k] = sum_j T_k(z_ij); out = (1/N) s@C + bo.
// 256 blocks x 512 thr: block = 4 rows x 4 warps/row (j-split 128 each).
// 2 blocks/SM x 16 warps = 32 warps/SM resident (occ ~65%); single wave.
// 4 independent lat-4 recurrence chains per lane; one inner pass.
// ---------------------------------------------------------------------------
__global__ __launch_bounds__(512, 2) void cheb_main_kernel(
    const float* __restrict__ x, const float* __restrict__ bo,
    float* __restrict__ out)
{
    __shared__ float sx[NN * 2];
    __shared__ float sred[16][DD];         // per-warp reduced s
    __shared__ float sredc[4][DD];         // per-row combined s

    const float inv_hd = g_inv_hd;         // published by prologue

    const int b = blockIdx.x >> 7;         // 128 blocks per batch
    // stage x via float4 (1024 floats = 256 float4)
    for (int t = threadIdx.x; t < NN * 2 / 4; t += 512)
        reinterpret_cast<float4*>(sx)[t] =
            reinterpret_cast<const float4*>(x + b * NN * 2)[t];
    __syncthreads();

    const int w    = threadIdx.x >> 5;     // warp 0..15
    const int lane = threadIdx.x & 31;
    const int r    = w >> 2;               // row-in-block 0..3
    const int h    = w & 3;                // j-quarter 0..3
    const int i    = ((blockIdx.x & 127) << 2) + r;   // row within batch
    const float xi0 = sx[2 * i], xi1 = sx[2 * i + 1];

    float s[DD];
    {
        const int j0 = h * 128;
        const int ja = j0 + lane, jb = ja + 32, jc = ja + 64, jd = ja + 96;
        float dxa = xi0 - sx[2 * ja], dya = xi1 - sx[2 * ja + 1];
        float dxb = xi0 - sx[2 * jb], dyb = xi1 - sx[2 * jb + 1];
        float dxc = xi0 - sx[2 * jc], dyc = xi1 - sx[2 * jc + 1];
        float dxd = xi0 - sx[2 * jd], dyd = xi1 - sx[2 * jd + 1];
        float za = fmaf(sqrtf(fmaf(dxa, dxa, dya * dya)), inv_hd, -1.0f);
        float zb = fmaf(sqrtf(fmaf(dxb, dxb, dyb * dyb)), inv_hd, -1.0f);
        float zc = fmaf(sqrtf(fmaf(dxc, dxc, dyc * dyc)), inv_hd, -1.0f);
        float zd = fmaf(sqrtf(fmaf(dxd, dxd, dyd * dyd)), inv_hd, -1.0f);
        za = fminf(fmaxf(za, -1.0f), 1.0f);
        zb = fminf(fmaxf(zb, -1.0f), 1.0f);
        zc = fminf(fmaxf(zc, -1.0f), 1.0f);
        zd = fminf(fmaxf(zd, -1.0f), 1.0f);

        s[0] = 4.0f;                       // T_0 == 1, 4 source nodes per lane
        s[1] = (za + zb) + (zc + zd);
        float t0a = 1.0f, t1a = za, z2a = za + za;
        float t0b = 1.0f, t1b = zb, z2b = zb + zb;
        float t0c = 1.0f, t1c = zc, z2c = zc + zc;
        float t0d = 1.0f, t1d = zd, z2d = zd + zd;
        #pragma unroll
        for (int k = 2; k < DD; k++) {
            float ta = fmaf(z2a, t1a, -t0a); t0a = t1a; t1a = ta;
            float tb = fmaf(z2b, t1b, -t0b); t0b = t1b; t1b = tb;
            float tc = fmaf(z2c, t1c, -t0c); t0c = t1c; t1c = tc;
            float td = fmaf(z2d, t1d, -t0d); t0d = t1d; t1d = td;
            s[k] = (ta + tb) + (tc + td);
        }
    }

    // reduce-scatter butterfly, explicit stage lengths: lane ends with k = lane
    #pragma unroll
    for (int st = 0; st < 5; st++) {
        const int off = 16 >> st;          // 16,8,4,2,1 (compile-time per stage)
        const int len = 16 >> st;
        const bool hi = (lane & off) != 0;
        #pragma unroll
        for (int k = 0; k < len; k++) {
            float send = hi ? s[k] : s[k + len];
            float recv = __shfl_xor_sync(0xffffffffu, send, off);
            s[k] = (hi ? s[k + len] : s[k]) + recv;
        }
    }
    sred[w][lane] = s[0];
    __syncthreads();

    // combine the 4 j-quarters per row (deterministic sequential order)
    if (threadIdx.x < 4 * DD) {
        const int rr = threadIdx.x >> 5, kk = threadIdx.x & 31;
        sredc[rr][kk] = ((sred[4 * rr][kk]     + sred[4 * rr + 1][kk])
                       + (sred[4 * rr + 2][kk] + sred[4 * rr + 3][kk]))
                        * (1.0f / (float)NN);
    }
    __syncthreads();

    // contract with C: warp owns 32 columns, lane owns 1 (coalesced LDG of C)
    const int c0 = h * 32 + lane;
    float acc = bo[c0];
    #pragma unroll
    for (int k = 0; k < DD; k++)
        acc = fmaf(sredc[r][k], g_C[k * HID + c0], acc);
    const int gi = b * NN + i;
    out[gi * HID + c0] = acc;
}

// ---------------------------------------------------------------------------
// Launch: 2 graph-capturable kernels.
// Input order: x, W1_0,b1_0,W2_0,b2_0, W1_1,b1_1,W2_1,b2_1, W1_2,b1_2,W2_2,b2_2, Wo,bo
// ---------------------------------------------------------------------------
extern "C" void kernel_launch(void* const* d_in, const int* in_sizes, int n_in,
                              void* d_out, int out_size)
{
    const float* x   = (const float*)d_in[0];
    const float* W10 = (const float*)d_in[1];
    const float* b10 = (const float*)d_in[2];
    const float* W20 = (const float*)d_in[3];
    const float* b20 = (const float*)d_in[4];
    const float* W11 = (const float*)d_in[5];
    const float* b11 = (const float*)d_in[6];
    const float* W21 = (const float*)d_in[7];
    const float* b21 = (const float*)d_in[8];
    const float* W12 = (const float*)d_in[9];
    const float* b12 = (const float*)d_in[10];
    const float* W22 = (const float*)d_in[11];
    const float* b22 = (const float*)d_in[12];
    const float* Wo  = (const float*)d_in[13];
    const float* bo  = (const float*)d_in[14];
    float* out = (float*)d_out;

    prologue_kernel<<<NE_BLOCKS, NE_THREADS>>>(x, W10, b10, W20, b20, W11, b11,
                                               W21, b21, W12, b12, W22, b22, Wo);
    cheb_main_kernel<<<(BB * NN) / 4, 512>>>(x, bo, out);
}